// round 14
// baseline (speedup 1.0000x reference)
#include <cuda_runtime.h>
#include <cuda_fp16.h>
#include <cstdint>

// Problem constants (fixed by setup_inputs)
#define BATCH   8
#define HH      128
#define WW      128
#define CC      256
#define HID     64
#define NTOK    (HH*WW)          // 16384 tokens per batch
#define NP      1024
#define KKEEP   768
#define TOK_ALL (BATCH*NTOK)     // 131072
#define BM      256
#define NBLK    (TOK_ALL/BM)     // 512
#define NSTEPS  16
#define THREADS 512              // 16 warps, m16n64 each

// Scratch (device globals — no allocation allowed)
__device__ float    g_imp[TOK_ALL];
__device__ unsigned g_ball[BATCH*32];

// ---------------- SMEM layout (bytes) ----------------
// BH/BL: w1 hi/lo, 8x8-tile blocked fp16 (tile idx = k8*8+n8, 128B/tile): 32KB each.
// BL must sit at BH+32768 (fused hi/lo LDSM addressing via lane>>4).
// AST: per-warp 6-stage cp.async ring; stage = 16 rows x 80B pitch = 1280B.
#define OFF_BH   0
#define OFF_BL   32768
#define OFF_B1   65536
#define OFF_W2   65792
#define OFF_AST  66048
#define WARP_AST 7680            // 6 * 1280
#define STAGE_B  1280
#define SMEM_SZ  (66048 + 16*WARP_AST)   // 188928

// ---------------- asm helpers ----------------
static __device__ __forceinline__ uint32_t smem_u32(const void* p) {
    uint32_t a;
    asm("{ .reg .u64 t; cvta.to.shared.u64 t, %1; cvt.u32.u64 %0, t; }" : "=r"(a) : "l"(p));
    return a;
}
static __device__ __forceinline__ uint32_t h2u(__half2 h) {
    return *reinterpret_cast<uint32_t*>(&h);
}
#define LDSM_X4T(r, a) \
    asm volatile("ldmatrix.sync.aligned.m8n8.x4.trans.shared.b16 {%0,%1,%2,%3}, [%4];" \
        : "=r"((r)[0]), "=r"((r)[1]), "=r"((r)[2]), "=r"((r)[3]) : "r"(a))
#define MMA16816(d, a, b) \
    asm volatile("mma.sync.aligned.m16n8k16.row.col.f32.f16.f16.f32 " \
        "{%0,%1,%2,%3}, {%4,%5,%6,%7}, {%8,%9}, {%0,%1,%2,%3};" \
        : "+f"((d)[0]), "+f"((d)[1]), "+f"((d)[2]), "+f"((d)[3]) \
        : "r"((a)[0]), "r"((a)[1]), "r"((a)[2]), "r"((a)[3]), "r"((b)[0]), "r"((b)[1]))
#define CP_ASYNC16(dst, src) \
    asm volatile("cp.async.cg.shared.global [%0], [%1], 16;" \
                 :: "r"(dst), "l"(src) : "memory")
#define CP_COMMIT() asm volatile("cp.async.commit_group;" ::: "memory")
#define CP_WAIT(n)  asm volatile("cp.async.wait_group %0;" :: "n"(n) : "memory")
#define LDS64F(f0, f1, a) \
    asm volatile("ld.shared.v2.f32 {%0,%1}, [%2];" : "=f"(f0), "=f"(f1) : "r"(a))

static __device__ __forceinline__ float gelu_exact(float v) {
    return 0.5f * v * (1.0f + erff(v * 0.7071067811865476f));
}

// split one float2 into hi/lo fp16x2 register pair
static __device__ __forceinline__ void split_f2(float2 v, uint32_t& hi, uint32_t& lo) {
    __half2 h = __floats2half2_rn(v.x, v.y);
    float2 hf = __half22float2(h);
    __half2 l = __floats2half2_rn(v.x - hf.x, v.y - hf.y);
    hi = h2u(h); lo = h2u(l);
}

// issue one warp-private A stage: 16 rows x 16 floats of k16 step `s`
static __device__ __forceinline__ void issue_stage(
    uint32_t stage_base, const float* aw, int s, int lane)
{
#pragma unroll
    for (int i = 0; i < 2; ++i) {
        int idx = lane + i * 32;
        int r = idx >> 2, q = idx & 3;
        uint32_t dst = stage_base + (uint32_t)(r * 80 + q * 16);
        const float* src = aw + (size_t)r * CC + s * 16 + q * 4;
        CP_ASYNC16(dst, src);
    }
}

// ============ Kernel A: fp16-split HMMA MLP -> per-token importance ============
// H = gelu(X[131072,256] @ W1[256,64] + b1); imp = sigmoid(H @ w2 + b2)
// 3-product fp16 split (err ~1e-7 << score order-stat gaps).
// 16 free-running warps (m16n64), warp-private 6-stage cp.async rings,
// no mainloop block barriers; per step B LDSMs are hoisted ABOVE the A
// LDS/split chain so LDSM latency hides under the ~24-op split.
__global__ __launch_bounds__(THREADS, 1) void score_mma(
    const float* __restrict__ tokens,
    const float* __restrict__ w1,
    const float* __restrict__ b1,
    const float* __restrict__ w2,
    const float* __restrict__ b2)
{
    extern __shared__ char sm[];
    const uint32_t sb = smem_u32(sm);
    const int tid = threadIdx.x;
    const int lane = tid & 31, wid = tid >> 5;      // 16 warps
    const int g = lane >> 2, tig = lane & 3;

    if (tid < 64) {
        ((float*)(sm + OFF_B1))[tid] = b1[tid];
        ((float*)(sm + OFF_W2))[tid] = w2[tid];
    }
    const float b2v = b2[0];

    // stage w1 hi/lo once: tile idx (k>>3)*8 + (n>>3), byte (k&7)*16 + (n&7)*2
#pragma unroll
    for (int j = 0; j < 16; ++j) {
        int pi = tid + j * THREADS;                 // 8192 half2 pairs
        int k = pi >> 5, n = (pi & 31) * 2;
        float2 v = *(const float2*)(w1 + k * HID + n);
        uint32_t hb, lb;
        split_f2(v, hb, lb);
        uint32_t off = (uint32_t)(((k >> 3) * 8 + (n >> 3)) * 128 + (k & 7) * 16 + (n & 7) * 2);
        *(uint32_t*)(sm + OFF_BH + off) = hb;
        *(uint32_t*)(sm + OFF_BL + off) = lb;
    }

    // A cp.async ring
    const uint32_t ast = sb + OFF_AST + (uint32_t)wid * WARP_AST;
    const float* aw = tokens + (size_t)(blockIdx.x * BM + wid * 16) * CC;

    // prologue: fill stages 0..4 (5 groups)
#pragma unroll
    for (int st = 0; st < 5; ++st) {
        issue_stage(ast + st * STAGE_B, aw, st, lane);
        CP_COMMIT();
    }
    __syncthreads();    // the ONLY block barrier; B is read-only hereafter

    // B fused hi/lo ldmatrix base: lanes 16-31 fetch the BL copies
    const uint32_t b_base = sb + OFF_BH + (uint32_t)(lane >> 4) * 32768u
                          + (uint32_t)((lane >> 3) & 1) * 1024u
                          + (uint32_t)(lane & 7) * 16u;

    // fragment read offsets within a stage (80B pitch -> conflict-free)
    uint32_t foff[4];
#pragma unroll
    for (int q = 0; q < 4; ++q)
        foff[q] = (uint32_t)((((q & 1) << 3) + g) * 80
                             + ((tig * 2 + ((q >> 1) << 3)) << 2));

    float acc[8][4];
#pragma unroll
    for (int nt = 0; nt < 8; ++nt)
#pragma unroll
        for (int q = 0; q < 4; ++q) acc[nt][q] = 0.0f;

#pragma unroll
    for (int s = 0; s < NSTEPS; ++s) {              // 16 k16 steps
        CP_WAIT(4);                                 // current stage complete
        __syncwarp();

        // hoist ALL B LDSMs first — latency hides under the A split chain
        uint32_t b4[8][4];                          // {bh0,bh1,bl0,bl1} per nt
#pragma unroll
        for (int nt = 0; nt < 8; ++nt)
            LDSM_X4T(b4[nt], b_base + (uint32_t)((s * 16 + nt) * 128));

        const uint32_t stg = ast + (uint32_t)((s % 6) * STAGE_B);
        uint32_t ah[4], al[4];
#pragma unroll
        for (int q = 0; q < 4; ++q) {
            float2 v;
            LDS64F(v.x, v.y, stg + foff[q]);
            split_f2(v, ah[q], al[q]);
        }

        // refill ring 5 ahead; empty commit in tail keeps group accounting fixed
        if (s + 5 < NSTEPS)
            issue_stage(ast + (uint32_t)(((s + 5) % 6) * STAGE_B), aw, s + 5, lane);
        CP_COMMIT();

        // product-major MMA stream (acc reuse distance = 8)
#pragma unroll
        for (int nt = 0; nt < 8; ++nt)
            MMA16816(acc[nt], ah, b4[nt]);          // hi*hi
#pragma unroll
        for (int nt = 0; nt < 8; ++nt)
            MMA16816(acc[nt], ah, b4[nt] + 2);      // hi*lo
#pragma unroll
        for (int nt = 0; nt < 8; ++nt)
            MMA16816(acc[nt], al, b4[nt]);          // lo*hi
    }

    // ---- epilogue: gelu(h+b1)*w2, reduce 64 cols, sigmoid ----
    const float* b1s = (const float*)(sm + OFF_B1);
    const float* w2s = (const float*)(sm + OFF_W2);
    float p0 = 0.0f, p1 = 0.0f;
#pragma unroll
    for (int nt = 0; nt < 8; ++nt) {
        int c0 = nt * 8 + tig * 2, c1 = c0 + 1;
        float bb0 = b1s[c0], bb1 = b1s[c1];
        float ww0 = w2s[c0], ww1 = w2s[c1];
        p0 += gelu_exact(acc[nt][0] + bb0) * ww0 + gelu_exact(acc[nt][1] + bb1) * ww1;
        p1 += gelu_exact(acc[nt][2] + bb0) * ww0 + gelu_exact(acc[nt][3] + bb1) * ww1;
    }
    p0 += __shfl_xor_sync(0xffffffffu, p0, 1);
    p0 += __shfl_xor_sync(0xffffffffu, p0, 2);
    p1 += __shfl_xor_sync(0xffffffffu, p1, 1);
    p1 += __shfl_xor_sync(0xffffffffu, p1, 2);
    if (tig == 0) {
        int r0 = blockIdx.x * BM + wid * 16 + g;
        g_imp[r0]     = 1.0f / (1.0f + expf(-(p0 + b2v)));
        g_imp[r0 + 8] = 1.0f / (1.0f + expf(-(p1 + b2v)));
    }
}

// ============ Kernel B: fused patch-scores + stable top-768 -> ballots ============
// 64 blocks x 128 thr (8 blocks/batch). Each block recomputes its batch's 1024
// patch sums into smem (first block DRAM, rest L2 hits), then ranks 128 patches.
__global__ __launch_bounds__(128) void select_kernel()
{
    __shared__ float sk[NP];
    const int b = blockIdx.x >> 3;
    const int tid = threadIdx.x;
    const int p = (blockIdx.x & 7) * 128 + tid;
    const float* base = g_imp + b * NTOK;

#pragma unroll
    for (int i = 0; i < 8; ++i) {
        int pp = tid + i * 128;
        int pr = pp >> 5, pc = pp & 31;
        float sum = 0.0f;
#pragma unroll
        for (int r = 0; r < 4; ++r) {
            float4 v = *(const float4*)(base + (pr * 4 + r) * WW + pc * 4);
            sum += (v.x + v.y) + (v.z + v.w);
        }
        sk[pp] = sum;                    // monotone in mean; ranking identical
    }
    __syncthreads();

    const float kp = sk[p];
    int rank = 0;
    const float4* s4 = (const float4*)sk;
#pragma unroll 4
    for (int j4 = 0; j4 < NP / 4; ++j4) {
        float4 v = s4[j4];
        int j = j4 * 4;
        rank += (int)((v.x > kp) || (v.x == kp && (j + 0) < p));
        rank += (int)((v.y > kp) || (v.y == kp && (j + 1) < p));
        rank += (int)((v.z > kp) || (v.z == kp && (j + 2) < p));
        rank += (int)((v.w > kp) || (v.w == kp && (j + 3) < p));
    }
    const unsigned mask = __ballot_sync(0xffffffffu, rank < KKEEP);
    if ((tid & 31) == 0)
        g_ball[b * 32 + (p >> 5)] = mask;
}

// ============ Kernel C: ballot-decode + gather + spatial reassembly (R7-proven) ============
__global__ __launch_bounds__(128) void gather_kernel(
    const float* __restrict__ tokens, float* __restrict__ out)
{
    const int k = blockIdx.x;            // kept slot 0..767
    const int b = blockIdx.y;
    __shared__ int s_p;

    if (threadIdx.x < 32) {
        const int w = threadIdx.x;
        unsigned bal = g_ball[b * 32 + w];
        int cnt = __popc(bal);
        int pre = cnt;
#pragma unroll
        for (int d = 1; d < 32; d <<= 1) {
            int t = __shfl_up_sync(0xffffffffu, pre, d);
            if (w >= d) pre += t;
        }
        pre -= cnt;                      // exclusive prefix of kept count
        if (k >= pre && k < pre + cnt) {
            int bit = __fns(bal, 0, (k - pre) + 1);
            s_p = w * 32 + bit;
        }
    }
    __syncthreads();
    const int p = s_p;
    const int pr = p >> 5, pc = p & 31;
    const int kr = k >> 5, kc = k & 31;

    const float4* src = (const float4*)(tokens + (size_t)b * NTOK * CC);
    float4*       dst = (float4*)(out + (size_t)b * (KKEEP * 16) * CC);
    const int t = threadIdx.x;

#pragma unroll
    for (int i = 0; i < 4; i++) {
        size_t so   = (size_t)((pr * 4 + i) * WW + pc * 4) * (CC / 4);
        size_t dofs = (size_t)((kr * 4 + i) * WW + kc * 4) * (CC / 4);
#pragma unroll
        for (int it = 0; it < 2; it++) {
            int e = it * 128 + t;
            dst[dofs + e] = src[so + e];
        }
    }
}

// ============================ launch ============================
extern "C" void kernel_launch(void* const* d_in, const int* in_sizes, int n_in,
                              void* d_out, int out_size)
{
    const float* tokens = (const float*)d_in[0];
    const float* w1 = (const float*)d_in[1];
    const float* b1 = (const float*)d_in[2];
    const float* w2 = (const float*)d_in[3];
    const float* b2 = (const float*)d_in[4];
    (void)in_sizes; (void)n_in; (void)out_size;

    cudaFuncSetAttribute(score_mma, cudaFuncAttributeMaxDynamicSharedMemorySize, SMEM_SZ);
    score_mma<<<NBLK, THREADS, SMEM_SZ>>>(tokens, w1, b1, w2, b2);
    select_kernel<<<64, 128>>>();
    gather_kernel<<<dim3(KKEEP, BATCH), 128>>>(tokens, (float*)d_out);
}

// round 15
// speedup vs baseline: 1.0493x; 1.0493x over previous
#include <cuda_runtime.h>
#include <cuda_fp16.h>
#include <cstdint>

// Problem constants (fixed by setup_inputs)
#define BATCH   8
#define HH      128
#define WW      128
#define CC      256
#define HID     64
#define NTOK    (HH*WW)          // 16384 tokens per batch
#define NP      1024
#define KKEEP   768
#define TOK_ALL (BATCH*NTOK)     // 131072
#define BM      256
#define NBLK    (TOK_ALL/BM)     // 512
#define NSTEPS  16
#define THREADS 512              // 16 warps, m16n64 each

// Scratch (device globals — no allocation allowed)
__device__ float    g_imp[TOK_ALL];
__device__ unsigned g_key[BATCH*NP];
__device__ unsigned g_ball[BATCH*32];

// ---------------- SMEM layout (bytes) ----------------
// BH/BL: w1 hi/lo, 8x8-tile blocked fp16 (tile idx = k8*8+n8, 128B/tile): 32KB each.
// BL must sit at BH+32768 (fused hi/lo LDSM addressing via lane>>4).
// AST: per-warp 6-stage cp.async ring; stage = 16 rows x 80B pitch = 1280B.
#define OFF_BH   0
#define OFF_BL   32768
#define OFF_B1   65536
#define OFF_W2   65792
#define OFF_AST  66048
#define WARP_AST 7680            // 6 * 1280
#define STAGE_B  1280
#define SMEM_SZ  (66048 + 16*WARP_AST)   // 188928

// ---------------- asm helpers ----------------
static __device__ __forceinline__ uint32_t smem_u32(const void* p) {
    uint32_t a;
    asm("{ .reg .u64 t; cvta.to.shared.u64 t, %1; cvt.u32.u64 %0, t; }" : "=r"(a) : "l"(p));
    return a;
}
static __device__ __forceinline__ uint32_t h2u(__half2 h) {
    return *reinterpret_cast<uint32_t*>(&h);
}
#define LDSM_X4T(r, a) \
    asm volatile("ldmatrix.sync.aligned.m8n8.x4.trans.shared.b16 {%0,%1,%2,%3}, [%4];" \
        : "=r"((r)[0]), "=r"((r)[1]), "=r"((r)[2]), "=r"((r)[3]) : "r"(a))
#define MMA16816(d, a, b) \
    asm volatile("mma.sync.aligned.m16n8k16.row.col.f32.f16.f16.f32 " \
        "{%0,%1,%2,%3}, {%4,%5,%6,%7}, {%8,%9}, {%0,%1,%2,%3};" \
        : "+f"((d)[0]), "+f"((d)[1]), "+f"((d)[2]), "+f"((d)[3]) \
        : "r"((a)[0]), "r"((a)[1]), "r"((a)[2]), "r"((a)[3]), "r"((b)[0]), "r"((b)[1]))
#define CP_ASYNC16(dst, src) \
    asm volatile("cp.async.cg.shared.global [%0], [%1], 16;" \
                 :: "r"(dst), "l"(src) : "memory")
#define CP_COMMIT() asm volatile("cp.async.commit_group;" ::: "memory")
#define CP_WAIT(n)  asm volatile("cp.async.wait_group %0;" :: "n"(n) : "memory")
#define LDS64F(f0, f1, a) \
    asm volatile("ld.shared.v2.f32 {%0,%1}, [%2];" : "=f"(f0), "=f"(f1) : "r"(a))

static __device__ __forceinline__ float gelu_exact(float v) {
    return 0.5f * v * (1.0f + erff(v * 0.7071067811865476f));
}

// split one float2 into hi/lo fp16x2 register pair
static __device__ __forceinline__ void split_f2(float2 v, uint32_t& hi, uint32_t& lo) {
    __half2 h = __floats2half2_rn(v.x, v.y);
    float2 hf = __half22float2(h);
    __half2 l = __floats2half2_rn(v.x - hf.x, v.y - hf.y);
    hi = h2u(h); lo = h2u(l);
}

// issue one warp-private A stage: 16 rows x 16 floats of k16 step `s`
static __device__ __forceinline__ void issue_stage(
    uint32_t stage_base, const float* aw, int s, int lane)
{
#pragma unroll
    for (int i = 0; i < 2; ++i) {
        int idx = lane + i * 32;
        int r = idx >> 2, q = idx & 3;
        uint32_t dst = stage_base + (uint32_t)(r * 80 + q * 16);
        const float* src = aw + (size_t)r * CC + s * 16 + q * 4;
        CP_ASYNC16(dst, src);
    }
}

// ============ Kernel A: fp16-split HMMA MLP -> per-token importance (R14-best) ============
// H = gelu(X[131072,256] @ W1[256,64] + b1); imp = sigmoid(H @ w2 + b2)
// 3-product fp16 split (err ~1e-7 << score order-stat gaps).
// 16 free-running warps (m16n64), warp-private 6-stage cp.async rings,
// no mainloop block barriers; B LDSMs hoisted above the A LDS/split chain.
__global__ __launch_bounds__(THREADS, 1) void score_mma(
    const float* __restrict__ tokens,
    const float* __restrict__ w1,
    const float* __restrict__ b1,
    const float* __restrict__ w2,
    const float* __restrict__ b2)
{
    extern __shared__ char sm[];
    const uint32_t sb = smem_u32(sm);
    const int tid = threadIdx.x;
    const int lane = tid & 31, wid = tid >> 5;      // 16 warps
    const int g = lane >> 2, tig = lane & 3;

    if (tid < 64) {
        ((float*)(sm + OFF_B1))[tid] = b1[tid];
        ((float*)(sm + OFF_W2))[tid] = w2[tid];
    }
    const float b2v = b2[0];

    // stage w1 hi/lo once: tile idx (k>>3)*8 + (n>>3), byte (k&7)*16 + (n&7)*2
#pragma unroll
    for (int j = 0; j < 16; ++j) {
        int pi = tid + j * THREADS;                 // 8192 half2 pairs
        int k = pi >> 5, n = (pi & 31) * 2;
        float2 v = *(const float2*)(w1 + k * HID + n);
        uint32_t hb, lb;
        split_f2(v, hb, lb);
        uint32_t off = (uint32_t)(((k >> 3) * 8 + (n >> 3)) * 128 + (k & 7) * 16 + (n & 7) * 2);
        *(uint32_t*)(sm + OFF_BH + off) = hb;
        *(uint32_t*)(sm + OFF_BL + off) = lb;
    }

    // A cp.async ring
    const uint32_t ast = sb + OFF_AST + (uint32_t)wid * WARP_AST;
    const float* aw = tokens + (size_t)(blockIdx.x * BM + wid * 16) * CC;

    // prologue: fill stages 0..4 (5 groups)
#pragma unroll
    for (int st = 0; st < 5; ++st) {
        issue_stage(ast + st * STAGE_B, aw, st, lane);
        CP_COMMIT();
    }
    __syncthreads();    // the ONLY block barrier; B is read-only hereafter

    // B fused hi/lo ldmatrix base: lanes 16-31 fetch the BL copies
    const uint32_t b_base = sb + OFF_BH + (uint32_t)(lane >> 4) * 32768u
                          + (uint32_t)((lane >> 3) & 1) * 1024u
                          + (uint32_t)(lane & 7) * 16u;

    // fragment read offsets within a stage (80B pitch -> conflict-free)
    uint32_t foff[4];
#pragma unroll
    for (int q = 0; q < 4; ++q)
        foff[q] = (uint32_t)((((q & 1) << 3) + g) * 80
                             + ((tig * 2 + ((q >> 1) << 3)) << 2));

    float acc[8][4];
#pragma unroll
    for (int nt = 0; nt < 8; ++nt)
#pragma unroll
        for (int q = 0; q < 4; ++q) acc[nt][q] = 0.0f;

#pragma unroll
    for (int s = 0; s < NSTEPS; ++s) {              // 16 k16 steps
        CP_WAIT(4);                                 // current stage complete
        __syncwarp();

        // hoist ALL B LDSMs first — latency hides under the A split chain
        uint32_t b4[8][4];                          // {bh0,bh1,bl0,bl1} per nt
#pragma unroll
        for (int nt = 0; nt < 8; ++nt)
            LDSM_X4T(b4[nt], b_base + (uint32_t)((s * 16 + nt) * 128));

        const uint32_t stg = ast + (uint32_t)((s % 6) * STAGE_B);
        uint32_t ah[4], al[4];
#pragma unroll
        for (int q = 0; q < 4; ++q) {
            float2 v;
            LDS64F(v.x, v.y, stg + foff[q]);
            split_f2(v, ah[q], al[q]);
        }

        // refill ring 5 ahead; empty commit in tail keeps group accounting fixed
        if (s + 5 < NSTEPS)
            issue_stage(ast + (uint32_t)(((s + 5) % 6) * STAGE_B), aw, s + 5, lane);
        CP_COMMIT();

        // product-major MMA stream (acc reuse distance = 8)
#pragma unroll
        for (int nt = 0; nt < 8; ++nt)
            MMA16816(acc[nt], ah, b4[nt]);          // hi*hi
#pragma unroll
        for (int nt = 0; nt < 8; ++nt)
            MMA16816(acc[nt], ah, b4[nt] + 2);      // hi*lo
#pragma unroll
        for (int nt = 0; nt < 8; ++nt)
            MMA16816(acc[nt], al, b4[nt]);          // lo*hi
    }

    // ---- epilogue: gelu(h+b1)*w2, reduce 64 cols, sigmoid ----
    const float* b1s = (const float*)(sm + OFF_B1);
    const float* w2s = (const float*)(sm + OFF_W2);
    float p0 = 0.0f, p1 = 0.0f;
#pragma unroll
    for (int nt = 0; nt < 8; ++nt) {
        int c0 = nt * 8 + tig * 2, c1 = c0 + 1;
        float bb0 = b1s[c0], bb1 = b1s[c1];
        float ww0 = w2s[c0], ww1 = w2s[c1];
        p0 += gelu_exact(acc[nt][0] + bb0) * ww0 + gelu_exact(acc[nt][1] + bb1) * ww1;
        p1 += gelu_exact(acc[nt][2] + bb0) * ww0 + gelu_exact(acc[nt][3] + bb1) * ww1;
    }
    p0 += __shfl_xor_sync(0xffffffffu, p0, 1);
    p0 += __shfl_xor_sync(0xffffffffu, p0, 2);
    p1 += __shfl_xor_sync(0xffffffffu, p1, 1);
    p1 += __shfl_xor_sync(0xffffffffu, p1, 2);
    if (tig == 0) {
        int r0 = blockIdx.x * BM + wid * 16 + g;
        g_imp[r0]     = 1.0f / (1.0f + expf(-(p0 + b2v)));
        g_imp[r0 + 8] = 1.0f / (1.0f + expf(-(p1 + b2v)));
    }
}

// ============ Kernel B1: patch scores -> ordered-uint keys (R7-proven) ============
__global__ __launch_bounds__(256) void pscore_kernel()
{
    const int pg = blockIdx.x * 256 + threadIdx.x;   // 8192 patches
    const int b = pg >> 10, p = pg & (NP - 1);
    const int pr = p >> 5, pc = p & 31;
    const float* base = g_imp + b * NTOK;
    float sum = 0.0f;
#pragma unroll
    for (int i = 0; i < 4; i++) {
        float4 v = *(const float4*)(base + (pr * 4 + i) * WW + pc * 4);
        sum += (v.x + v.y) + (v.z + v.w);
    }
    g_key[pg] = __float_as_uint(sum);   // sums of sigmoids > 0: uint order == float order
}

// ============ Kernel B2: stable top-768 rank -> keep ballots (R7-proven) ============
__global__ __launch_bounds__(128) void rank_kernel()
{
    __shared__ unsigned sk[NP];
    const int b = blockIdx.x >> 3;
    const int tid = threadIdx.x;
    const int p = (blockIdx.x & 7) * 128 + tid;

#pragma unroll
    for (int i = 0; i < 8; ++i)
        sk[tid + i * 128] = g_key[b * NP + tid + i * 128];
    __syncthreads();

    const unsigned kp = sk[p];
    int rank = 0;
    const uint4* s4 = (const uint4*)sk;
#pragma unroll 4
    for (int j4 = 0; j4 < NP / 4; ++j4) {
        uint4 v = s4[j4];
        int j = j4 * 4;
        rank += (int)((v.x > kp) || (v.x == kp && (j + 0) < p));
        rank += (int)((v.y > kp) || (v.y == kp && (j + 1) < p));
        rank += (int)((v.z > kp) || (v.z == kp && (j + 2) < p));
        rank += (int)((v.w > kp) || (v.w == kp && (j + 3) < p));
    }
    const unsigned mask = __ballot_sync(0xffffffffu, rank < KKEEP);
    if ((tid & 31) == 0)
        g_ball[b * 32 + (p >> 5)] = mask;
}

// ============ Kernel C: ballot-decode + gather + spatial reassembly (R7-proven) ============
__global__ __launch_bounds__(128) void gather_kernel(
    const float* __restrict__ tokens, float* __restrict__ out)
{
    const int k = blockIdx.x;            // kept slot 0..767
    const int b = blockIdx.y;
    __shared__ int s_p;

    if (threadIdx.x < 32) {
        const int w = threadIdx.x;
        unsigned bal = g_ball[b * 32 + w];
        int cnt = __popc(bal);
        int pre = cnt;
#pragma unroll
        for (int d = 1; d < 32; d <<= 1) {
            int t = __shfl_up_sync(0xffffffffu, pre, d);
            if (w >= d) pre += t;
        }
        pre -= cnt;                      // exclusive prefix of kept count
        if (k >= pre && k < pre + cnt) {
            int bit = __fns(bal, 0, (k - pre) + 1);
            s_p = w * 32 + bit;
        }
    }
    __syncthreads();
    const int p = s_p;
    const int pr = p >> 5, pc = p & 31;
    const int kr = k >> 5, kc = k & 31;

    const float4* src = (const float4*)(tokens + (size_t)b * NTOK * CC);
    float4*       dst = (float4*)(out + (size_t)b * (KKEEP * 16) * CC);
    const int t = threadIdx.x;

#pragma unroll
    for (int i = 0; i < 4; i++) {
        size_t so   = (size_t)((pr * 4 + i) * WW + pc * 4) * (CC / 4);
        size_t dofs = (size_t)((kr * 4 + i) * WW + kc * 4) * (CC / 4);
#pragma unroll
        for (int it = 0; it < 2; it++) {
            int e = it * 128 + t;
            dst[dofs + e] = src[so + e];
        }
    }
}

// ============================ launch ============================
extern "C" void kernel_launch(void* const* d_in, const int* in_sizes, int n_in,
                              void* d_out, int out_size)
{
    const float* tokens = (const float*)d_in[0];
    const float* w1 = (const float*)d_in[1];
    const float* b1 = (const float*)d_in[2];
    const float* w2 = (const float*)d_in[3];
    const float* b2 = (const float*)d_in[4];
    (void)in_sizes; (void)n_in; (void)out_size;

    cudaFuncSetAttribute(score_mma, cudaFuncAttributeMaxDynamicSharedMemorySize, SMEM_SZ);
    score_mma<<<NBLK, THREADS, SMEM_SZ>>>(tokens, w1, b1, w2, b2);
    pscore_kernel<<<BATCH * NP / 256, 256>>>();
    rank_kernel<<<64, 128>>>();
    gather_kernel<<<dim3(KKEEP, BATCH), 128>>>(tokens, (float*)d_out);
}